// round 14
// baseline (speedup 1.0000x reference)
#include <cuda_runtime.h>
#include <cuda_fp16.h>
#include <math.h>
#include <cstdint>

// ---------------------------------------------------------------------------
// DAFCN forward, B=1024, T=50, F=48, D=512.
// Attention branch dead: combined[:,:,:10] = gcn_out only.
// R14: layer kernel stage loads via cp.async.bulk (2 bulk ops/stage instead of
//      896 LDGSTS: R13 profiling showed LDGSTS issue = 100% of layer runtime).
//      Operands stored k-slab-contiguous. m-tile 192, n-tile 128, 512 thr.
// ---------------------------------------------------------------------------

typedef unsigned long long ull;

#define PI_F 3.14159265358979f
#define W0_DCT 0.18257418583505537f
#define W1_DCT 0.2581988897471611f
#define NB 1024
#define MROWS (NB * 48)

// g_Af layout: [slab=k/32][row][k%32]  (slab-contiguous for bulk copy)
// g_Wh layout: [l][slab][n][k%32]
__device__ float  g_X[MROWS * 512];       // fp32 y (residual carrier)
__device__ __half g_Af[MROWS * 512];
__device__ __half g_Wh[4 * 512 * 512];
__device__ float  g_dct[NB * 480];
__device__ float  g_ffc[NB * 480];

// ---- helpers --------------------------------------------------------------
__device__ __forceinline__ ull pk2(float lo, float hi) {
    ull r; asm("mov.b64 %0, {%1, %2};" : "=l"(r) : "f"(lo), "f"(hi)); return r;
}
__device__ __forceinline__ void fma2f(ull &d, ull a, ull b) {
    asm("fma.rn.f32x2 %0, %1, %2, %0;" : "+l"(d) : "l"(a), "l"(b));
}
__device__ __forceinline__ float2 up2(ull v) {
    float lo, hi; asm("mov.b64 {%0, %1}, %2;" : "=f"(lo), "=f"(hi) : "l"(v));
    return make_float2(lo, hi);
}
__device__ __forceinline__ uint32_t smem_u32(const void* p) {
    uint32_t a;
    asm("{ .reg .u64 t; cvta.to.shared.u64 t, %1; cvt.u32.u64 %0, t; }"
        : "=r"(a) : "l"(p));
    return a;
}
__device__ __forceinline__ float ftanh(float x) {
    return 1.0f - __fdividef(2.0f, __expf(2.0f * x) + 1.0f);
}

#define MBARRIER_INIT(addr, cnt) \
    asm volatile("mbarrier.init.shared.b64 [%0], %1;" :: "r"(addr), "r"(cnt) : "memory")
#define MBARRIER_EXPECT_TX(addr, bytes) \
    asm volatile("mbarrier.arrive.expect_tx.shared.b64 _, [%0], %1;" \
                 :: "r"(addr), "r"(bytes) : "memory")
#define MBAR_WAIT(a, ph) do { \
    uint32_t _m = (a), _p = (ph), _d; \
    asm volatile("{\n\t.reg .pred p;\n\t" \
        "mbarrier.try_wait.parity.acquire.cta.shared::cta.b64 p, [%1], %2;\n\t" \
        "selp.b32 %0, 1, 0, p;\n\t}" : "=r"(_d) : "r"(_m), "r"(_p) : "memory"); \
    if (!_d) { \
        asm volatile("{\n\t.reg .pred P1;\n\tWL_%=:\n\t" \
            "mbarrier.try_wait.parity.acquire.cta.shared::cta.b64 P1, [%0], %1, 0x989680;\n\t" \
            "@P1 bra.uni WD_%=;\n\tbra.uni WL_%=;\n\tWD_%=:\n\t}" \
            :: "r"(_m), "r"(_p) : "memory"); \
    } } while (0)

#define BULK_G2S(dst, src, bytes, mbar) \
    asm volatile("cp.async.bulk.shared::cluster.global.mbarrier::complete_tx::bytes " \
                 "[%0], [%1], %2, [%3];" \
        :: "r"((uint32_t)(dst)), "l"(src), "r"((uint32_t)(bytes)), \
           "r"((uint32_t)(mbar)) : "memory")

#define LDSM4(r, addr) \
    asm volatile("ldmatrix.sync.aligned.m8n8.x4.shared.b16 {%0,%1,%2,%3}, [%4];" \
        : "=r"((r)[0]), "=r"((r)[1]), "=r"((r)[2]), "=r"((r)[3]) : "r"(addr))

__device__ __forceinline__ void mma_f16(float* d, const uint32_t* a,
                                        const uint32_t* b) {
    asm volatile(
        "mma.sync.aligned.m16n8k16.row.col.f32.f16.f16.f32 "
        "{%0,%1,%2,%3}, {%4,%5,%6,%7}, {%8,%9}, {%0,%1,%2,%3};"
        : "+f"(d[0]), "+f"(d[1]), "+f"(d[2]), "+f"(d[3])
        : "r"(a[0]), "r"(a[1]), "r"(a[2]), "r"(a[3]), "r"(b[0]), "r"(b[1]));
}

__device__ __forceinline__ size_t af_idx(int row, int col) {
    return ((size_t)(col >> 5) * MROWS + row) * 32 + (col & 31);
}

// ======================= prep_w: W^T fp16, slab-contiguous ================
__global__ void prep_w_kernel(const float* __restrict__ gcb_w) {
    int idx = blockIdx.x * 256 + threadIdx.x;
    int l = idx >> 18, k = (idx >> 9) & 511, n = idx & 511;
    float w = gcb_w[l * 262144 + k * 512 + n];
    size_t dst = (((size_t)l * 16 + (k >> 5)) * 512 + n) * 32 + (k & 31);
    g_Wh[dst] = __float2half_rn(w);
}

// ======================= head: FFC + gc1 (1 block / batch) =================
__global__ void __launch_bounds__(512)
head_kernel(const float* __restrict__ seq,
            const float* __restrict__ wl,  const float* __restrict__ wg,
            const float* __restrict__ gc1_w, const float* __restrict__ gc1_att,
            const float* __restrict__ gc1_b) {
    __shared__ float sSeq[2400];
    __shared__ float sc[60], ss[60];
    __shared__ float sV[16][6][31];
    __shared__ float sWg[36], sWl[9];
    __shared__ float sDct[480], sZ1[480];

    const int tid = threadIdx.x, b = blockIdx.x;

    for (int i = tid; i < 2400; i += 512) sSeq[i] = seq[b * 2400 + i];
    if (tid < 60) {
        float a = 6.283185307179586f * (float)tid / 60.0f;
        sc[tid] = cosf(a); ss[tid] = sinf(a);
    }
    if (tid < 36) sWg[tid] = wg[tid];
    if (tid < 9)  sWl[tid] = wl[tid];
    __syncthreads();

    if ((tid & 31) < 31) {
        const int g = tid >> 5, k = tid & 31;
        float re0=0,re1=0,re2=0,im0=0,im1=0,im2=0;
        int idx = 0;
        for (int t = 0; t < 60; t++) {
            int tsrc = (t < 50) ? t : 49;
            float co = sc[idx], si = ss[idx];
            float x0 = sSeq[tsrc * 48 + g];
            float x1 = sSeq[tsrc * 48 + 16 + g];
            float x2 = sSeq[tsrc * 48 + 32 + g];
            re0 += x0*co; im0 -= x0*si;
            re1 += x1*co; im1 -= x1*si;
            re2 += x2*co; im2 -= x2*si;
            idx += k; if (idx >= 60) idx -= 60;
        }
        float U[6] = {re0, re1, re2, im0, im1, im2};
        #pragma unroll
        for (int o = 0; o < 6; o++) {
            float a = 0.f;
            #pragma unroll
            for (int c = 0; c < 6; c++) a += sWg[o * 6 + c] * U[c];
            sV[g][o][k] = (a > 0.f) ? a : 0.f;
        }
    }
    __syncthreads();

    if (tid < 480) {
        const int g = tid / 30, r = tid % 30, o = r / 10, t = r % 10;
        float spec = sV[g][o][0] + ((t & 1) ? -sV[g][o][30] : sV[g][o][30]);
        int idx = t;
        for (int k = 1; k < 30; k++) {
            spec += 2.0f * (sV[g][o][k] * sc[idx] - sV[g][o + 3][k] * ss[idx]);
            idx += t; if (idx >= 60) idx -= 60;
        }
        float v = spec * (1.0f / 60.0f);
        #pragma unroll
        for (int c = 0; c < 3; c++) v += sWl[o * 3 + c] * sSeq[t * 48 + c * 16 + g];
        g_ffc[b * 480 + (o * 16 + g) * 10 + t] = v;
    }

    if (tid < 480) {
        int f = tid % 48, d = tid / 48;
        float wd = (d == 0) ? W0_DCT : W1_DCT;
        float acc = 0.f, Sd = 0.f;
        for (int k = 0; k < 30; k++) {
            float cv = wd * cosf(PI_F * ((float)k + 0.5f) * (float)d / 30.0f);
            if (k < 10) acc += cv * sSeq[(40 + k) * 48 + f];
            else        Sd  += cv;
        }
        acc += Sd * sSeq[49 * 48 + f];
        sDct[f * 10 + d] = acc;
        g_dct[b * 480 + f * 10 + d] = acc;
    }
    __syncthreads();
    if (tid < 480) {
        int n = tid / 10, d = tid % 10;
        float a = 0.f;
        for (int m = 0; m < 48; m++) a += __ldg(gc1_att + n * 48 + m) * sDct[m * 10 + d];
        sZ1[n * 10 + d] = a;
    }
    __syncthreads();
    {
        float w10[10];
        #pragma unroll
        for (int d = 0; d < 10; d++) w10[d] = __ldg(gc1_w + d * 512 + tid);
        float bb = __ldg(gc1_b + tid);
        int slab = tid >> 5, kin = tid & 31;
        for (int n = 0; n < 48; n++) {
            float a = bb;
            #pragma unroll
            for (int d = 0; d < 10; d++) a += w10[d] * sZ1[n * 10 + d];
            float v = ftanh(a);
            int row = b * 48 + n;
            g_X[(size_t)row * 512 + tid] = v;
            g_Af[((size_t)slab * MROWS + row) * 32 + kin] = __float2half_rn(v);
        }
    }
}

// ===========================================================================
// Layer kernel: fp16 HMMA, cp.async.bulk 4-buffer pipeline (2 ops/stage),
// m-tile 192 (4 batches), n-tile 128, fused att+bias+tanh epilogue in SMEM.
// ===========================================================================
#define A_BYTES (192 * 64)            // 12288 per stage
#define B_BYTES (128 * 64)            // 8192 per stage
#define STG_BYTES (A_BYTES + B_BYTES) // 20480
#define SG_BYTES (192 * 132 * 4)      // 101376
#define ATT_BYTES (2304 * 4)          // 9216
#define MBAR_OFF (SG_BYTES + ATT_BYTES)  // 110592 (past sG+attT; stages 0..81920)
#define GEMM_SMEM (MBAR_OFF + 64)     // 110656

__global__ void __launch_bounds__(512, 1)
layer_kernel(int layer, int residual, int emit,
             const float* __restrict__ att, const float* __restrict__ bias) {
    extern __shared__ __align__(128) char smem[];
    const int tid = threadIdx.x;
    const int lane = tid & 31, wid = tid >> 5;
    const int wm = wid >> 2, wn = wid & 3;      // wm 0..3 (48 rows), wn 0..3 (32 cols)
    const int n0 = blockIdx.x * 128;
    const int m0 = blockIdx.y * 192;
    const uint32_t sbase = smem_u32(smem);
    const uint32_t mb = sbase + MBAR_OFF;

    const __half* Aslab = g_Af;                               // [16][MROWS][32]
    const __half* Wslab = g_Wh + (size_t)layer * 16 * 512 * 32;  // [16][512][32]

    if (tid == 0) {
        #pragma unroll
        for (int i = 0; i < 4; i++) MBARRIER_INIT(mb + i * 8, 1);
    }
    __syncthreads();

    if (tid == 0) {
        #pragma unroll
        for (int s = 0; s < 3; s++) {
            uint32_t stg = sbase + s * STG_BYTES;
            MBARRIER_EXPECT_TX(mb + s * 8, STG_BYTES);
            BULK_G2S(stg,           Aslab + ((size_t)s * MROWS + m0) * 32,
                     A_BYTES, mb + s * 8);
            BULK_G2S(stg + A_BYTES, Wslab + ((size_t)s * 512 + n0) * 32,
                     B_BYTES, mb + s * 8);
        }
    }

    float acc[3][4][4];
    #pragma unroll
    for (int i = 0; i < 3; i++)
        #pragma unroll
        for (int j = 0; j < 4; j++)
            #pragma unroll
            for (int r = 0; r < 4; r++) acc[i][j][r] = 0.f;

    const int arow = wm * 48 + (lane & 15);
    const int acol = (lane >> 4) * 8;
    const int brow = wn * 32 + (lane & 7) + ((lane >> 4) & 1) * 8;
    const int bcol = ((lane >> 3) & 1) * 8;

    #pragma unroll 1
    for (int ks = 0; ks < 16; ks++) {
        int buf = ks & 3;
        MBAR_WAIT(mb + buf * 8, (ks >> 2) & 1);
        __syncthreads();   // all warps done reading buffer (ks-1)&3
        if (ks + 3 < 16 && tid == 0) {
            int s = ks + 3, b2 = s & 3;
            uint32_t stg = sbase + b2 * STG_BYTES;
            MBARRIER_EXPECT_TX(mb + b2 * 8, STG_BYTES);
            BULK_G2S(stg,           Aslab + ((size_t)s * MROWS + m0) * 32,
                     A_BYTES, mb + b2 * 8);
            BULK_G2S(stg + A_BYTES, Wslab + ((size_t)s * 512 + n0) * 32,
                     B_BYTES, mb + b2 * 8);
        }

        uint32_t base = sbase + buf * STG_BYTES;
        #pragma unroll
        for (int sub = 0; sub < 2; sub++) {
            int kb = sub * 16;
            uint32_t ah[3][4], bh[2][4];
            #pragma unroll
            for (int mt = 0; mt < 3; mt++)
                LDSM4(ah[mt], base + (uint32_t)((arow + mt * 16) * 64 + (kb + acol) * 2));
            #pragma unroll
            for (int ng = 0; ng < 2; ng++)
                LDSM4(bh[ng], base + A_BYTES + (uint32_t)((brow + ng * 16) * 64 + (kb + bcol) * 2));
            #pragma unroll
            for (int mt = 0; mt < 3; mt++) {
                #pragma unroll
                for (int nf = 0; nf < 4; nf++)
                    mma_f16(acc[mt][nf], ah[mt], &bh[nf >> 1][(nf & 1) * 2]);
            }
        }
    }
    __syncthreads();   // mainloop done; stage buffers become sG

    // ================= fused epilogue: att @ G + bias + tanh ===============
    float* sG = (float*)smem;                 // 192 x 132 fp32
    float* sAttT = sG + 192 * 132;            // 48 x 48

    #pragma unroll
    for (int mt = 0; mt < 3; mt++) {
        int row = wm * 48 + mt * 16 + (lane >> 2);
        #pragma unroll
        for (int nf = 0; nf < 4; nf++) {
            int col = wn * 32 + nf * 8 + (lane & 3) * 2;
            sG[row * 132 + col]           = acc[mt][nf][0];
            sG[row * 132 + col + 1]       = acc[mt][nf][1];
            sG[(row + 8) * 132 + col]     = acc[mt][nf][2];
            sG[(row + 8) * 132 + col + 1] = acc[mt][nf][3];
        }
    }
    for (int i = tid; i < 2304; i += 512) {
        int m = i / 48, n = i % 48;
        sAttT[m * 48 + n] = __ldg(att + n * 48 + m);
    }
    __syncthreads();

    {
        const int lc = tid & 127;             // local col 0..127
        const int b4 = tid >> 7;              // local batch 0..3
        float g[48];
        #pragma unroll
        for (int m = 0; m < 48; m++) g[m] = sG[(b4 * 48 + m) * 132 + lc];

        ull gacc[24];
        #pragma unroll
        for (int j = 0; j < 24; j++) gacc[j] = 0ull;
        #pragma unroll 4
        for (int m = 0; m < 48; m++) {
            ull gp = pk2(g[m], g[m]);
            const ull* ap = (const ull*)(sAttT + m * 48);
            #pragma unroll
            for (int j = 0; j < 24; j++) fma2f(gacc[j], ap[j], gp);
        }

        const int col = n0 + lc;
        const float bb = __ldg(bias + col);
        const int rbase = m0 + b4 * 48;
        #pragma unroll
        for (int j = 0; j < 24; j++) {
            float2 z = up2(gacc[j]);
            float v0 = ftanh(z.x + bb);
            float v1 = ftanh(z.y + bb);
            int r0 = rbase + 2 * j, r1 = r0 + 1;
            size_t x0 = (size_t)r0 * 512 + col, x1 = (size_t)r1 * 512 + col;
            if (residual) {
                v0 += g_X[x0];
                v1 += g_X[x1];
                g_X[x0] = v0;
                g_X[x1] = v1;
            }
            if (emit) {
                g_Af[af_idx(r0, col)] = __float2half_rn(v0);
                g_Af[af_idx(r1, col)] = __float2half_rn(v1);
            }
        }
    }
}

// ======================= tail: gc7 + fused + MLP (warp-dot) ================
#define TAIL_SMEM ((24576 + 5120 + 480 + 480 + 480 + 1920 + 2560) * 4)
__global__ void __launch_bounds__(512)
tail_kernel(const float* __restrict__ gc7_w, const float* __restrict__ gc7_att,
            const float* __restrict__ gc7_b, const float* __restrict__ mlp_w1,
            const float* __restrict__ mlp_w2, float* __restrict__ out) {
    extern __shared__ float sm[];
    float* sY    = sm;              // 24576 (reused as sH later)
    float* sW7   = sm + 24576;      // 5120 [o][k]
    float* sDct  = sm + 29696;      // 480
    float* sP    = sm + 30176;      // 480
    float* sOut  = sm + 30656;      // 480
    float* sFused= sm + 31136;      // 1920
    float* sW2   = sm + 33056;      // 2560 [t2][o]
    float* sH    = sm;              // overlay

    const int tid = threadIdx.x, b = blockIdx.x;
    const int lane = tid & 31, w = tid >> 5;

    {
        const float4* ysrc = (const float4*)(g_X + (size_t)b * 24576);
        float4* ydst = (float4*)sY;
        #pragma unroll
        for (int i = 0; i < 12; i++) ydst[tid + i * 512] = ysrc[tid + i * 512];
    }
    for (int i = tid; i < 5120; i += 512) {
        int o = i >> 9, k = i & 511;
        sW7[i] = __ldg(gc7_w + k * 10 + o);
    }
    for (int i = tid; i < 2560; i += 512) sW2[i] = __ldg(mlp_w2 + i);
    if (tid < 480) sDct[tid] = g_dct[b * 480 + tid];
    __syncthreads();

    #pragma unroll 1
    for (int uu = 0; uu < 30; uu++) {
        int u = uu * 16 + w;
        int m = u / 10, o = u % 10;
        const float* yr = sY + m * 512;
        const float* wr = sW7 + o * 512;
        float a = 0.f;
        #pragma unroll
        for (int j = 0; j < 16; j++) a += yr[j * 32 + lane] * wr[j * 32 + lane];
        a += __shfl_xor_sync(0xFFFFFFFFu, a, 16);
        a += __shfl_xor_sync(0xFFFFFFFFu, a, 8);
        a += __shfl_xor_sync(0xFFFFFFFFu, a, 4);
        a += __shfl_xor_sync(0xFFFFFFFFu, a, 2);
        a += __shfl_xor_sync(0xFFFFFFFFu, a, 1);
        if (lane == 0) sP[u] = a;
    }
    __syncthreads();

    if (tid < 480) {
        int n = tid / 10, o = tid % 10;
        float a = __ldg(gc7_b + o) + sDct[tid];
        for (int m = 0; m < 48; m++) a += __ldg(gc7_att + n * 48 + m) * sP[m * 10 + o];
        sOut[tid] = a;
    }
    __syncthreads();

    for (int i = tid; i < 1920; i += 512) {
        int f = i % 48, t = i / 48;
        float v;
        if (t < 30) {
            v = 0.f;
            #pragma unroll
            for (int d = 0; d < 10; d++) {
                float wd = (d == 0) ? W0_DCT : W1_DCT;
                v += wd * cosf(PI_F * ((float)t + 0.5f) * (float)d / 30.0f)
                        * sOut[f * 10 + d];
            }
        } else v = g_ffc[b * 480 + f * 10 + (t - 30)];
        sFused[f * 40 + t] = v;
    }
    __syncthreads();

    {
        int o = tid & 255, fg = tid >> 8;
        float w1r[40];
        #pragma unroll
        for (int t = 0; t < 40; t++) w1r[t] = __ldg(mlp_w1 + o * 40 + t);
        for (int f = fg * 24; f < fg * 24 + 24; f++) {
            float a = 0.f;
            #pragma unroll
            for (int t = 0; t < 40; t++) a += w1r[t] * sFused[f * 40 + t];
            sH[f * 256 + o] = (a > 0.f) ? a : 0.f;
        }
    }
    __syncthreads();

    #pragma unroll 1
    for (int uu = 0; uu < 30; uu++) {
        int u = uu * 16 + w;
        int f = u / 10, t2 = u % 10;
        const float* hr = sH + f * 256;
        const float* wr = sW2 + t2 * 256;
        float a = 0.f;
        #pragma unroll
        for (int j = 0; j < 8; j++) a += hr[j * 32 + lane] * wr[j * 32 + lane];
        a += __shfl_xor_sync(0xFFFFFFFFu, a, 16);
        a += __shfl_xor_sync(0xFFFFFFFFu, a, 8);
        a += __shfl_xor_sync(0xFFFFFFFFu, a, 4);
        a += __shfl_xor_sync(0xFFFFFFFFu, a, 2);
        a += __shfl_xor_sync(0xFFFFFFFFu, a, 1);
        if (lane == 0) out[b * 480 + t2 * 48 + f] = a;
    }
}

// ===========================================================================
extern "C" void kernel_launch(void* const* d_in, const int* in_sizes, int n_in,
                              void* d_out, int out_size) {
    const float* seq     = (const float*)d_in[0];
    const float* gc1_w   = (const float*)d_in[5];
    const float* gc1_att = (const float*)d_in[6];
    const float* gc1_b   = (const float*)d_in[7];
    const float* gcb_w   = (const float*)d_in[8];
    const float* gcb_att = (const float*)d_in[9];
    const float* gcb_b   = (const float*)d_in[10];
    const float* gc7_w   = (const float*)d_in[11];
    const float* gc7_att = (const float*)d_in[12];
    const float* gc7_b   = (const float*)d_in[13];
    const float* mlp_w1  = (const float*)d_in[14];
    const float* mlp_w2  = (const float*)d_in[15];
    const float* ffc_wl  = (const float*)d_in[16];
    const float* ffc_wg  = (const float*)d_in[17];
    float* out = (float*)d_out;

    int B = in_sizes[0] / 2400;           // 1024
    int gm = (B * 48) / 192;              // 256 m-tiles (4 batches each)

    cudaFuncSetAttribute(layer_kernel,
        cudaFuncAttributeMaxDynamicSharedMemorySize, GEMM_SMEM);
    cudaFuncSetAttribute(tail_kernel,
        cudaFuncAttributeMaxDynamicSharedMemorySize, TAIL_SMEM);

    prep_w_kernel<<<4096, 256>>>(gcb_w);
    head_kernel<<<B, 512>>>(seq, ffc_wl, ffc_wg, gc1_w, gc1_att, gc1_b);

    for (int l = 0; l < 4; l++) {
        layer_kernel<<<dim3(4, gm), 512, GEMM_SMEM>>>(
            l, l & 1, (l < 3) ? 1 : 0,
            gcb_att + l * 2304, gcb_b + l * 512);
    }
    tail_kernel<<<B, 512, TAIL_SMEM>>>(gc7_w, gc7_att, gc7_b,
                                       mlp_w1, mlp_w2, out);
}

// round 15
// speedup vs baseline: 1.2858x; 1.2858x over previous
#include <cuda_runtime.h>
#include <cuda_fp16.h>
#include <math.h>
#include <cstdint>

// ---------------------------------------------------------------------------
// DAFCN forward, B=1024, T=50, F=48, D=512.
// Attention branch dead: combined[:,:,:10] = gcn_out only.
// R15: cp.async.bulk stage loads (0 LDGSTS) with GMEM-pre-swizzled operand
//      layouts (chunk ^= row&3 per 64B row) so LDSM stays near-conflict-free;
//      R12 tile shape restored (256 thr, m96/n128, 4 stages, 2 CTA/SM).
// ---------------------------------------------------------------------------

typedef unsigned long long ull;

#define PI_F 3.14159265358979f
#define W0_DCT 0.18257418583505537f
#define W1_DCT 0.2581988897471611f
#define NB 1024
#define MROWS (NB * 48)

// g_Af: [slab=k/32][row][swizzled 32 halfs], swizzle: chunk ^= row&3
// g_Wh: [l][slab][n][swizzled 32 halfs],     swizzle: chunk ^= n&3
__device__ float  g_X[MROWS * 512];       // fp32 y (residual carrier)
__device__ __half g_Af[MROWS * 512];
__device__ __half g_Wh[4 * 512 * 512];
__device__ float  g_dct[NB * 480];
__device__ float  g_ffc[NB * 480];

// ---- helpers --------------------------------------------------------------
__device__ __forceinline__ ull pk2(float lo, float hi) {
    ull r; asm("mov.b64 %0, {%1, %2};" : "=l"(r) : "f"(lo), "f"(hi)); return r;
}
__device__ __forceinline__ void fma2f(ull &d, ull a, ull b) {
    asm("fma.rn.f32x2 %0, %1, %2, %0;" : "+l"(d) : "l"(a), "l"(b));
}
__device__ __forceinline__ float2 up2(ull v) {
    float lo, hi; asm("mov.b64 {%0, %1}, %2;" : "=f"(lo), "=f"(hi) : "l"(v));
    return make_float2(lo, hi);
}
__device__ __forceinline__ uint32_t smem_u32(const void* p) {
    uint32_t a;
    asm("{ .reg .u64 t; cvta.to.shared.u64 t, %1; cvt.u32.u64 %0, t; }"
        : "=r"(a) : "l"(p));
    return a;
}
__device__ __forceinline__ float ftanh(float x) {
    return 1.0f - __fdividef(2.0f, __expf(2.0f * x) + 1.0f);
}
// swizzled index inside [slab][row][32] arrays
__device__ __forceinline__ size_t swz_idx(size_t rowbase, int row, int col) {
    int h = col & 31;
    int ch = ((h >> 3) ^ (row & 3));
    return rowbase * 32 + ch * 8 + (h & 7);
}

#define MBARRIER_INIT(addr, cnt) \
    asm volatile("mbarrier.init.shared.b64 [%0], %1;" :: "r"(addr), "r"(cnt) : "memory")
#define MBARRIER_EXPECT_TX(addr, bytes) \
    asm volatile("mbarrier.arrive.expect_tx.shared.b64 _, [%0], %1;" \
                 :: "r"(addr), "r"(bytes) : "memory")
#define MBAR_WAIT(a, ph) do { \
    uint32_t _m = (a), _p = (ph), _d; \
    asm volatile("{\n\t.reg .pred p;\n\t" \
        "mbarrier.try_wait.parity.acquire.cta.shared::cta.b64 p, [%1], %2;\n\t" \
        "selp.b32 %0, 1, 0, p;\n\t}" : "=r"(_d) : "r"(_m), "r"(_p) : "memory"); \
    if (!_d) { \
        asm volatile("{\n\t.reg .pred P1;\n\tWL_%=:\n\t" \
            "mbarrier.try_wait.parity.acquire.cta.shared::cta.b64 P1, [%0], %1, 0x989680;\n\t" \
            "@P1 bra.uni WD_%=;\n\tbra.uni WL_%=;\n\tWD_%=:\n\t}" \
            :: "r"(_m), "r"(_p) : "memory"); \
    } } while (0)

#define BULK_G2S(dst, src, bytes, mbar) \
    asm volatile("cp.async.bulk.shared::cluster.global.mbarrier::complete_tx::bytes " \
                 "[%0], [%1], %2, [%3];" \
        :: "r"((uint32_t)(dst)), "l"(src), "r"((uint32_t)(bytes)), \
           "r"((uint32_t)(mbar)) : "memory")

#define LDSM4(r, addr) \
    asm volatile("ldmatrix.sync.aligned.m8n8.x4.shared.b16 {%0,%1,%2,%3}, [%4];" \
        : "=r"((r)[0]), "=r"((r)[1]), "=r"((r)[2]), "=r"((r)[3]) : "r"(addr))

__device__ __forceinline__ void mma_f16(float* d, const uint32_t* a,
                                        const uint32_t* b) {
    asm volatile(
        "mma.sync.aligned.m16n8k16.row.col.f32.f16.f16.f32 "
        "{%0,%1,%2,%3}, {%4,%5,%6,%7}, {%8,%9}, {%0,%1,%2,%3};"
        : "+f"(d[0]), "+f"(d[1]), "+f"(d[2]), "+f"(d[3])
        : "r"(a[0]), "r"(a[1]), "r"(a[2]), "r"(a[3]), "r"(b[0]), "r"(b[1]));
}

// ======================= prep_w: W^T fp16, slab + swizzle ==================
__global__ void prep_w_kernel(const float* __restrict__ gcb_w) {
    int idx = blockIdx.x * 256 + threadIdx.x;
    int l = idx >> 18, k = (idx >> 9) & 511, n = idx & 511;
    float w = gcb_w[l * 262144 + k * 512 + n];
    size_t rowbase = ((size_t)l * 16 + (k >> 5)) * 512 + n;
    g_Wh[swz_idx(rowbase, n, k)] = __float2half_rn(w);
}

// ======================= head: FFC + gc1 (1 block / batch) =================
__global__ void __launch_bounds__(512)
head_kernel(const float* __restrict__ seq,
            const float* __restrict__ wl,  const float* __restrict__ wg,
            const float* __restrict__ gc1_w, const float* __restrict__ gc1_att,
            const float* __restrict__ gc1_b) {
    __shared__ float sSeq[2400];
    __shared__ float sc[60], ss[60];
    __shared__ float sV[16][6][31];
    __shared__ float sWg[36], sWl[9];
    __shared__ float sDct[480], sZ1[480];

    const int tid = threadIdx.x, b = blockIdx.x;

    for (int i = tid; i < 2400; i += 512) sSeq[i] = seq[b * 2400 + i];
    if (tid < 60) {
        float a = 6.283185307179586f * (float)tid / 60.0f;
        sc[tid] = cosf(a); ss[tid] = sinf(a);
    }
    if (tid < 36) sWg[tid] = wg[tid];
    if (tid < 9)  sWl[tid] = wl[tid];
    __syncthreads();

    if ((tid & 31) < 31) {
        const int g = tid >> 5, k = tid & 31;
        float re0=0,re1=0,re2=0,im0=0,im1=0,im2=0;
        int idx = 0;
        for (int t = 0; t < 60; t++) {
            int tsrc = (t < 50) ? t : 49;
            float co = sc[idx], si = ss[idx];
            float x0 = sSeq[tsrc * 48 + g];
            float x1 = sSeq[tsrc * 48 + 16 + g];
            float x2 = sSeq[tsrc * 48 + 32 + g];
            re0 += x0*co; im0 -= x0*si;
            re1 += x1*co; im1 -= x1*si;
            re2 += x2*co; im2 -= x2*si;
            idx += k; if (idx >= 60) idx -= 60;
        }
        float U[6] = {re0, re1, re2, im0, im1, im2};
        #pragma unroll
        for (int o = 0; o < 6; o++) {
            float a = 0.f;
            #pragma unroll
            for (int c = 0; c < 6; c++) a += sWg[o * 6 + c] * U[c];
            sV[g][o][k] = (a > 0.f) ? a : 0.f;
        }
    }
    __syncthreads();

    if (tid < 480) {
        const int g = tid / 30, r = tid % 30, o = r / 10, t = r % 10;
        float spec = sV[g][o][0] + ((t & 1) ? -sV[g][o][30] : sV[g][o][30]);
        int idx = t;
        for (int k = 1; k < 30; k++) {
            spec += 2.0f * (sV[g][o][k] * sc[idx] - sV[g][o + 3][k] * ss[idx]);
            idx += t; if (idx >= 60) idx -= 60;
        }
        float v = spec * (1.0f / 60.0f);
        #pragma unroll
        for (int c = 0; c < 3; c++) v += sWl[o * 3 + c] * sSeq[t * 48 + c * 16 + g];
        g_ffc[b * 480 + (o * 16 + g) * 10 + t] = v;
    }

    if (tid < 480) {
        int f = tid % 48, d = tid / 48;
        float wd = (d == 0) ? W0_DCT : W1_DCT;
        float acc = 0.f, Sd = 0.f;
        for (int k = 0; k < 30; k++) {
            float cv = wd * cosf(PI_F * ((float)k + 0.5f) * (float)d / 30.0f);
            if (k < 10) acc += cv * sSeq[(40 + k) * 48 + f];
            else        Sd  += cv;
        }
        acc += Sd * sSeq[49 * 48 + f];
        sDct[f * 10 + d] = acc;
        g_dct[b * 480 + f * 10 + d] = acc;
    }
    __syncthreads();
    if (tid < 480) {
        int n = tid / 10, d = tid % 10;
        float a = 0.f;
        for (int m = 0; m < 48; m++) a += __ldg(gc1_att + n * 48 + m) * sDct[m * 10 + d];
        sZ1[n * 10 + d] = a;
    }
    __syncthreads();
    {
        float w10[10];
        #pragma unroll
        for (int d = 0; d < 10; d++) w10[d] = __ldg(gc1_w + d * 512 + tid);
        float bb = __ldg(gc1_b + tid);
        const int slab = tid >> 5;
        for (int n = 0; n < 48; n++) {
            float a = bb;
            #pragma unroll
            for (int d = 0; d < 10; d++) a += w10[d] * sZ1[n * 10 + d];
            float v = ftanh(a);
            int row = b * 48 + n;
            g_X[(size_t)row * 512 + tid] = v;
            g_Af[swz_idx((size_t)slab * MROWS + row, row, tid)] = __float2half_rn(v);
        }
    }
}

// ===========================================================================
// Layer kernel: fp16 HMMA, cp.async.bulk 4-stage pipeline (2 bulk ops/stage),
// m-tile 96 (2 batches), n-tile 128, 256 threads, 2 CTA/SM,
// fused att+bias+tanh epilogue in SMEM.
// ===========================================================================
#define A_BYTES (96 * 64)             // 6144
#define B_BYTES (128 * 64)            // 8192
#define STG_BYTES (A_BYTES + B_BYTES) // 14336
#define MBAR_OFF (4 * STG_BYTES)      // 57344
#define GEMM_SMEM 60416               // >= max(57344+64, epilogue 59904)

__global__ void __launch_bounds__(256, 2)
layer_kernel(int layer, int residual, int emit,
             const float* __restrict__ att, const float* __restrict__ bias) {
    extern __shared__ __align__(128) char smem[];
    const int tid = threadIdx.x;
    const int lane = tid & 31, wid = tid >> 5;
    const int wm = wid >> 2, wn = wid & 3;
    const int n0 = blockIdx.x * 128;
    const int m0 = blockIdx.y * 96;
    const uint32_t sbase = smem_u32(smem);
    const uint32_t mb = sbase + MBAR_OFF;

    const __half* Aslab = g_Af;                                  // [16][MROWS][32]
    const __half* Wslab = g_Wh + (size_t)layer * 16 * 512 * 32;  // [16][512][32]

    if (tid == 0) {
        #pragma unroll
        for (int i = 0; i < 4; i++) MBARRIER_INIT(mb + i * 8, 1);
    }
    __syncthreads();

    if (tid == 0) {
        #pragma unroll
        for (int s = 0; s < 3; s++) {
            uint32_t stg = sbase + s * STG_BYTES;
            MBARRIER_EXPECT_TX(mb + s * 8, STG_BYTES);
            BULK_G2S(stg,           Aslab + ((size_t)s * MROWS + m0) * 32,
                     A_BYTES, mb + s * 8);
            BULK_G2S(stg + A_BYTES, Wslab + ((size_t)s * 512 + n0) * 32,
                     B_BYTES, mb + s * 8);
        }
    }

    float acc[3][4][4];
    #pragma unroll
    for (int i = 0; i < 3; i++)
        #pragma unroll
        for (int j = 0; j < 4; j++)
            #pragma unroll
            for (int r = 0; r < 4; r++) acc[i][j][r] = 0.f;

    const int arow = wm * 48 + (lane & 15);       // local A row
    const int acol = (lane >> 4) * 8;             // half offset 0/8
    const int brow = wn * 32 + (lane & 7) + ((lane >> 4) & 1) * 8;
    const int bcol = ((lane >> 3) & 1) * 8;

    #pragma unroll 1
    for (int ks = 0; ks < 16; ks++) {
        int buf = ks & 3;
        MBAR_WAIT(mb + buf * 8, (ks >> 2) & 1);
        __syncthreads();   // all warps past prev iter's MMA -> buf (ks-1)&3 reusable
        if (ks + 3 < 16 && tid == 0) {
            int s = ks + 3, b2 = s & 3;
            uint32_t stg = sbase + b2 * STG_BYTES;
            MBARRIER_EXPECT_TX(mb + b2 * 8, STG_BYTES);
            BULK_G2S(stg,           Aslab + ((size_t)s * MROWS + m0) * 32,
                     A_BYTES, mb + b2 * 8);
            BULK_G2S(stg + A_BYTES, Wslab + ((size_t)s * 512 + n0) * 32,
                     B_BYTES, mb + b2 * 8);
        }

        uint32_t base = sbase + buf * STG_BYTES;
        #pragma unroll
        for (int sub = 0; sub < 2; sub++) {
            int kb = sub * 16;
            uint32_t ah[3][4], bh[2][4];
            #pragma unroll
            for (int mt = 0; mt < 3; mt++) {
                int r = arow + mt * 16;
                int ch = ((kb + acol) >> 3) ^ (r & 3);
                LDSM4(ah[mt], base + (uint32_t)(r * 64 + ch * 16));
            }
            #pragma unroll
            for (int ng = 0; ng < 2; ng++) {
                int r = brow + ng * 16;
                int ch = ((kb + bcol) >> 3) ^ (r & 3);
                LDSM4(bh[ng], base + A_BYTES + (uint32_t)(r * 64 + ch * 16));
            }
            #pragma unroll
            for (int mt = 0; mt < 3; mt++) {
                #pragma unroll
                for (int nf = 0; nf < 4; nf++)
                    mma_f16(acc[mt][nf], ah[mt], &bh[nf >> 1][(nf & 1) * 2]);
            }
        }
    }
    __syncthreads();   // mainloop done; SMEM (incl. mbar region) repurposed

    // ================= fused epilogue: att @ G + bias + tanh ===============
    float* sG = (float*)smem;                 // 96 x 132 fp32 = 50688 B
    float* sAttT = sG + 96 * 132;             // + 9216 = 59904

    #pragma unroll
    for (int mt = 0; mt < 3; mt++) {
        int row = wm * 48 + mt * 16 + (lane >> 2);
        #pragma unroll
        for (int nf = 0; nf < 4; nf++) {
            int col = wn * 32 + nf * 8 + (lane & 3) * 2;
            sG[row * 132 + col]           = acc[mt][nf][0];
            sG[row * 132 + col + 1]       = acc[mt][nf][1];
            sG[(row + 8) * 132 + col]     = acc[mt][nf][2];
            sG[(row + 8) * 132 + col + 1] = acc[mt][nf][3];
        }
    }
    for (int i = tid; i < 2304; i += 256) {
        int m = i / 48, n = i % 48;
        sAttT[m * 48 + n] = __ldg(att + n * 48 + m);
    }
    __syncthreads();

    {
        const int lc = tid & 127;             // local col 0..127
        const int b2 = tid >> 7;              // local batch 0/1
        float g[48];
        #pragma unroll
        for (int m = 0; m < 48; m++) g[m] = sG[(b2 * 48 + m) * 132 + lc];

        ull gacc[24];
        #pragma unroll
        for (int j = 0; j < 24; j++) gacc[j] = 0ull;
        #pragma unroll 4
        for (int m = 0; m < 48; m++) {
            ull gp = pk2(g[m], g[m]);
            const ull* ap = (const ull*)(sAttT + m * 48);
            #pragma unroll
            for (int j = 0; j < 24; j++) fma2f(gacc[j], ap[j], gp);
        }

        const int col = n0 + lc;
        const int slab = col >> 5;
        const float bb = __ldg(bias + col);
        const int rbase = m0 + b2 * 48;
        #pragma unroll
        for (int j = 0; j < 24; j++) {
            float2 z = up2(gacc[j]);
            float v0 = ftanh(z.x + bb);
            float v1 = ftanh(z.y + bb);
            int r0 = rbase + 2 * j, r1 = r0 + 1;
            size_t x0 = (size_t)r0 * 512 + col, x1 = (size_t)r1 * 512 + col;
            if (residual) {
                v0 += g_X[x0];
                v1 += g_X[x1];
                g_X[x0] = v0;
                g_X[x1] = v1;
            }
            if (emit) {
                g_Af[swz_idx((size_t)slab * MROWS + r0, r0, col)] = __float2half_rn(v0);
                g_Af[swz_idx((size_t)slab * MROWS + r1, r1, col)] = __float2half_rn(v1);
            }
        }
    }
}

// ======================= tail: gc7 + fused + MLP (warp-dot) ================
#define TAIL_SMEM ((24576 + 5120 + 480 + 480 + 480 + 1920 + 2560) * 4)
__global__ void __launch_bounds__(512)
tail_kernel(const float* __restrict__ gc7_w, const float* __restrict__ gc7_att,
            const float* __restrict__ gc7_b, const float* __restrict__ mlp_w1,
            const float* __restrict__ mlp_w2, float* __restrict__ out) {
    extern __shared__ float sm[];
    float* sY    = sm;              // 24576 (reused as sH later)
    float* sW7   = sm + 24576;      // 5120 [o][k]
    float* sDct  = sm + 29696;      // 480
    float* sP    = sm + 30176;      // 480
    float* sOut  = sm + 30656;      // 480
    float* sFused= sm + 31136;      // 1920
    float* sW2   = sm + 33056;      // 2560 [t2][o]
    float* sH    = sm;              // overlay

    const int tid = threadIdx.x, b = blockIdx.x;
    const int lane = tid & 31, w = tid >> 5;

    {
        const float4* ysrc = (const float4*)(g_X + (size_t)b * 24576);
        float4* ydst = (float4*)sY;
        #pragma unroll
        for (int i = 0; i < 12; i++) ydst[tid + i * 512] = ysrc[tid + i * 512];
    }
    for (int i = tid; i < 5120; i += 512) {
        int o = i >> 9, k = i & 511;
        sW7[i] = __ldg(gc7_w + k * 10 + o);
    }
    for (int i = tid; i < 2560; i += 512) sW2[i] = __ldg(mlp_w2 + i);
    if (tid < 480) sDct[tid] = g_dct[b * 480 + tid];
    __syncthreads();

    #pragma unroll 1
    for (int uu = 0; uu < 30; uu++) {
        int u = uu * 16 + w;
        int m = u / 10, o = u % 10;
        const float* yr = sY + m * 512;
        const float* wr = sW7 + o * 512;
        float a = 0.f;
        #pragma unroll
        for (int j = 0; j < 16; j++) a += yr[j * 32 + lane] * wr[j * 32 + lane];
        a += __shfl_xor_sync(0xFFFFFFFFu, a, 16);
        a += __shfl_xor_sync(0xFFFFFFFFu, a, 8);
        a += __shfl_xor_sync(0xFFFFFFFFu, a, 4);
        a += __shfl_xor_sync(0xFFFFFFFFu, a, 2);
        a += __shfl_xor_sync(0xFFFFFFFFu, a, 1);
        if (lane == 0) sP[u] = a;
    }
    __syncthreads();

    if (tid < 480) {
        int n = tid / 10, o = tid % 10;
        float a = __ldg(gc7_b + o) + sDct[tid];
        for (int m = 0; m < 48; m++) a += __ldg(gc7_att + n * 48 + m) * sP[m * 10 + o];
        sOut[tid] = a;
    }
    __syncthreads();

    for (int i = tid; i < 1920; i += 512) {
        int f = i % 48, t = i / 48;
        float v;
        if (t < 30) {
            v = 0.f;
            #pragma unroll
            for (int d = 0; d < 10; d++) {
                float wd = (d == 0) ? W0_DCT : W1_DCT;
                v += wd * cosf(PI_F * ((float)t + 0.5f) * (float)d / 30.0f)
                        * sOut[f * 10 + d];
            }
        } else v = g_ffc[b * 480 + f * 10 + (t - 30)];
        sFused[f * 40 + t] = v;
    }
    __syncthreads();

    {
        int o = tid & 255, fg = tid >> 8;
        float w1r[40];
        #pragma unroll
        for (int t = 0; t < 40; t++) w1r[t] = __ldg(mlp_w1 + o * 40 + t);
        for (int f = fg * 24; f < fg * 24 + 24; f++) {
            float a = 0.f;
            #pragma unroll
            for (int t = 0; t < 40; t++) a += w1r[t] * sFused[f * 40 + t];
            sH[f * 256 + o] = (a > 0.f) ? a : 0.f;
        }
    }
    __syncthreads();

    #pragma unroll 1
    for (int uu = 0; uu < 30; uu++) {
        int u = uu * 16 + w;
        int f = u / 10, t2 = u % 10;
        const float* hr = sH + f * 256;
        const float* wr = sW2 + t2 * 256;
        float a = 0.f;
        #pragma unroll
        for (int j = 0; j < 8; j++) a += hr[j * 32 + lane] * wr[j * 32 + lane];
        a += __shfl_xor_sync(0xFFFFFFFFu, a, 16);
        a += __shfl_xor_sync(0xFFFFFFFFu, a, 8);
        a += __shfl_xor_sync(0xFFFFFFFFu, a, 4);
        a += __shfl_xor_sync(0xFFFFFFFFu, a, 2);
        a += __shfl_xor_sync(0xFFFFFFFFu, a, 1);
        if (lane == 0) out[b * 480 + t2 * 48 + f] = a;
    }
}

// ===========================================================================
extern "C" void kernel_launch(void* const* d_in, const int* in_sizes, int n_in,
                              void* d_out, int out_size) {
    const float* seq     = (const float*)d_in[0];
    const float* gc1_w   = (const float*)d_in[5];
    const float* gc1_att = (const float*)d_in[6];
    const float* gc1_b   = (const float*)d_in[7];
    const float* gcb_w   = (const float*)d_in[8];
    const float* gcb_att = (const float*)d_in[9];
    const float* gcb_b   = (const float*)d_in[10];
    const float* gc7_w   = (const float*)d_in[11];
    const float* gc7_att = (const float*)d_in[12];
    const float* gc7_b   = (const float*)d_in[13];
    const float* mlp_w1  = (const float*)d_in[14];
    const float* mlp_w2  = (const float*)d_in[15];
    const float* ffc_wl  = (const float*)d_in[16];
    const float* ffc_wg  = (const float*)d_in[17];
    float* out = (float*)d_out;

    int B = in_sizes[0] / 2400;           // 1024
    int gm = (B * 48) / 96;               // 512 m-tiles

    cudaFuncSetAttribute(layer_kernel,
        cudaFuncAttributeMaxDynamicSharedMemorySize, GEMM_SMEM);
    cudaFuncSetAttribute(tail_kernel,
        cudaFuncAttributeMaxDynamicSharedMemorySize, TAIL_SMEM);

    prep_w_kernel<<<4096, 256>>>(gcb_w);
    head_kernel<<<B, 512>>>(seq, ffc_wl, ffc_wg, gc1_w, gc1_att, gc1_b);

    for (int l = 0; l < 4; l++) {
        layer_kernel<<<dim3(4, gm), 256, GEMM_SMEM>>>(
            l, l & 1, (l < 3) ? 1 : 0,
            gcb_att + l * 2304, gcb_b + l * 512);
    }
    tail_kernel<<<B, 512, TAIL_SMEM>>>(gc7_w, gc7_att, gc7_b,
                                       mlp_w1, mlp_w2, out);
}

// round 16
// speedup vs baseline: 1.5374x; 1.1957x over previous
#include <cuda_runtime.h>
#include <cuda_fp16.h>
#include <math.h>
#include <cstdint>

// ---------------------------------------------------------------------------
// DAFCN forward, B=1024, T=50, F=48, D=512.
// Attention branch dead: combined[:,:,:10] = gcn_out only.
// R16: R12 mainloop (LDGSTS loader, best measured) + tensor-core epilogue:
//      att@G via a second small fp16 MMA (M=48,N=128,K=48) instead of the
//      scalar LDS.64/FFMA2 loop that dominated the epilogue cost.
// ---------------------------------------------------------------------------

typedef unsigned long long ull;

#define PI_F 3.14159265358979f
#define W0_DCT 0.18257418583505537f
#define W1_DCT 0.2581988897471611f
#define NB 1024
#define MROWS (NB * 48)

__device__ float  g_X[MROWS * 512];       // fp32 y (residual carrier)
__device__ __half g_Af[MROWS * 512];      // fp16 gemm A operand (row-major)
__device__ __half g_Wh[4 * 512 * 512];    // W^T [l][n][k] fp16
__device__ float  g_dct[NB * 480];
__device__ float  g_ffc[NB * 480];

// ---- helpers --------------------------------------------------------------
__device__ __forceinline__ uint32_t smem_u32(const void* p) {
    uint32_t a;
    asm("{ .reg .u64 t; cvta.to.shared.u64 t, %1; cvt.u32.u64 %0, t; }"
        : "=r"(a) : "l"(p));
    return a;
}
__device__ __forceinline__ float ftanh(float x) {
    return 1.0f - __fdividef(2.0f, __expf(2.0f * x) + 1.0f);
}

#define CPA16(dst, src) \
    asm volatile("cp.async.cg.shared.global [%0], [%1], 16;" \
                 :: "r"(dst), "l"(src))
#define CP_COMMIT() asm volatile("cp.async.commit_group;" ::: "memory")
#define CP_WAIT(n)  asm volatile("cp.async.wait_group %0;" :: "n"(n) : "memory")

#define LDSM4(r, addr) \
    asm volatile("ldmatrix.sync.aligned.m8n8.x4.shared.b16 {%0,%1,%2,%3}, [%4];" \
        : "=r"((r)[0]), "=r"((r)[1]), "=r"((r)[2]), "=r"((r)[3]) : "r"(addr))

__device__ __forceinline__ void mma_f16(float* d, const uint32_t* a,
                                        const uint32_t* b) {
    asm volatile(
        "mma.sync.aligned.m16n8k16.row.col.f32.f16.f16.f32 "
        "{%0,%1,%2,%3}, {%4,%5,%6,%7}, {%8,%9}, {%0,%1,%2,%3};"
        : "+f"(d[0]), "+f"(d[1]), "+f"(d[2]), "+f"(d[3])
        : "r"(a[0]), "r"(a[1]), "r"(a[2]), "r"(a[3]), "r"(b[0]), "r"(b[1]));
}

// ======================= prep_w: W^T fp16 ==================================
__global__ void prep_w_kernel(const float* __restrict__ gcb_w) {
    int idx = blockIdx.x * 256 + threadIdx.x;
    int l = idx >> 18, k = (idx >> 9) & 511, n = idx & 511;
    float w = gcb_w[l * 262144 + k * 512 + n];
    g_Wh[l * 262144 + n * 512 + k] = __float2half_rn(w);
}

// ======================= head: FFC + gc1 (1 block / batch) =================
__global__ void __launch_bounds__(512)
head_kernel(const float* __restrict__ seq,
            const float* __restrict__ wl,  const float* __restrict__ wg,
            const float* __restrict__ gc1_w, const float* __restrict__ gc1_att,
            const float* __restrict__ gc1_b) {
    __shared__ float sSeq[2400];
    __shared__ float sc[60], ss[60];
    __shared__ float sV[16][6][31];
    __shared__ float sWg[36], sWl[9];
    __shared__ float sDct[480], sZ1[480];

    const int tid = threadIdx.x, b = blockIdx.x;

    for (int i = tid; i < 2400; i += 512) sSeq[i] = seq[b * 2400 + i];
    if (tid < 60) {
        float a = 6.283185307179586f * (float)tid / 60.0f;
        sc[tid] = cosf(a); ss[tid] = sinf(a);
    }
    if (tid < 36) sWg[tid] = wg[tid];
    if (tid < 9)  sWl[tid] = wl[tid];
    __syncthreads();

    if ((tid & 31) < 31) {
        const int g = tid >> 5, k = tid & 31;
        float re0=0,re1=0,re2=0,im0=0,im1=0,im2=0;
        int idx = 0;
        for (int t = 0; t < 60; t++) {
            int tsrc = (t < 50) ? t : 49;
            float co = sc[idx], si = ss[idx];
            float x0 = sSeq[tsrc * 48 + g];
            float x1 = sSeq[tsrc * 48 + 16 + g];
            float x2 = sSeq[tsrc * 48 + 32 + g];
            re0 += x0*co; im0 -= x0*si;
            re1 += x1*co; im1 -= x1*si;
            re2 += x2*co; im2 -= x2*si;
            idx += k; if (idx >= 60) idx -= 60;
        }
        float U[6] = {re0, re1, re2, im0, im1, im2};
        #pragma unroll
        for (int o = 0; o < 6; o++) {
            float a = 0.f;
            #pragma unroll
            for (int c = 0; c < 6; c++) a += sWg[o * 6 + c] * U[c];
            sV[g][o][k] = (a > 0.f) ? a : 0.f;
        }
    }
    __syncthreads();

    if (tid < 480) {
        const int g = tid / 30, r = tid % 30, o = r / 10, t = r % 10;
        float spec = sV[g][o][0] + ((t & 1) ? -sV[g][o][30] : sV[g][o][30]);
        int idx = t;
        for (int k = 1; k < 30; k++) {
            spec += 2.0f * (sV[g][o][k] * sc[idx] - sV[g][o + 3][k] * ss[idx]);
            idx += t; if (idx >= 60) idx -= 60;
        }
        float v = spec * (1.0f / 60.0f);
        #pragma unroll
        for (int c = 0; c < 3; c++) v += sWl[o * 3 + c] * sSeq[t * 48 + c * 16 + g];
        g_ffc[b * 480 + (o * 16 + g) * 10 + t] = v;
    }

    if (tid < 480) {
        int f = tid % 48, d = tid / 48;
        float wd = (d == 0) ? W0_DCT : W1_DCT;
        float acc = 0.f, Sd = 0.f;
        for (int k = 0; k < 30; k++) {
            float cv = wd * cosf(PI_F * ((float)k + 0.5f) * (float)d / 30.0f);
            if (k < 10) acc += cv * sSeq[(40 + k) * 48 + f];
            else        Sd  += cv;
        }
        acc += Sd * sSeq[49 * 48 + f];
        sDct[f * 10 + d] = acc;
        g_dct[b * 480 + f * 10 + d] = acc;
    }
    __syncthreads();
    if (tid < 480) {
        int n = tid / 10, d = tid % 10;
        float a = 0.f;
        for (int m = 0; m < 48; m++) a += __ldg(gc1_att + n * 48 + m) * sDct[m * 10 + d];
        sZ1[n * 10 + d] = a;
    }
    __syncthreads();
    {
        float w10[10];
        #pragma unroll
        for (int d = 0; d < 10; d++) w10[d] = __ldg(gc1_w + d * 512 + tid);
        float bb = __ldg(gc1_b + tid);
        for (int n = 0; n < 48; n++) {
            float a = bb;
            #pragma unroll
            for (int d = 0; d < 10; d++) a += w10[d] * sZ1[n * 10 + d];
            float v = ftanh(a);
            size_t idx = (size_t)(b * 48 + n) * 512 + tid;
            g_X[idx] = v;
            g_Af[idx] = __float2half_rn(v);
        }
    }
}

// ===========================================================================
// Layer kernel: fp16 HMMA, R12 LDGSTS 4-stage pipeline, m-tile 96 (2 batch),
// n-tile 128, 256 threads, 2 CTA/SM. Epilogue: att@G as a second MMA.
// ===========================================================================
#define ASTR 40
#define STG_A  (96  * ASTR * 2)        // 7680 B
#define STG_B  (128 * ASTR * 2)        // 10240 B
#define STG_SZ (STG_A + STG_B)         // 17920 B
#define GEMM_SMEM (4 * STG_SZ)         // 71680 B (>= epilogue 38912)

__global__ void __launch_bounds__(256, 2)
layer_kernel(int layer, int residual, int emit,
             const float* __restrict__ att, const float* __restrict__ bias) {
    extern __shared__ __align__(16) char smem[];
    const int tid = threadIdx.x;
    const int lane = tid & 31, wid = tid >> 5;
    const int wm = wid >> 2, wn = wid & 3;
    const int n0 = blockIdx.x * 128;
    const int m0 = blockIdx.y * 96;
    const uint32_t sbase = smem_u32(smem);

    const __half* Af = g_Af;
    const __half* Wh = g_Wh + layer * 262144;

    float acc[3][4][4];
    #pragma unroll
    for (int i = 0; i < 3; i++)
        #pragma unroll
        for (int j = 0; j < 4; j++)
            #pragma unroll
            for (int r = 0; r < 4; r++) acc[i][j][r] = 0.f;

    #define LOAD_STAGE(buf, ks) do { \
        uint32_t stg = sbase + (buf) * STG_SZ; \
        _Pragma("unroll") \
        for (int it = 0; it < 4; it++) { \
            int i = it * 256 + tid; \
            if (it == 3 && tid >= 128) break; \
            int r = i >> 2, q = i & 3; \
            uint32_t dst; const __half* src; \
            if (r < 96) { \
                dst = stg + r * 80 + q * 16; \
                src = Af + (size_t)(m0 + r) * 512 + (ks) * 32 + q * 8; \
            } else { \
                dst = stg + STG_A + (r - 96) * 80 + q * 16; \
                src = Wh + (size_t)(n0 + r - 96) * 512 + (ks) * 32 + q * 8; \
            } \
            CPA16(dst, src); \
        } \
    } while (0)

    LOAD_STAGE(0, 0); CP_COMMIT();
    LOAD_STAGE(1, 1); CP_COMMIT();
    LOAD_STAGE(2, 2); CP_COMMIT();

    const int arow = wm * 48 + (lane & 15);
    const int acol = (lane >> 4) * 8;
    const int brow = wn * 32 + (lane & 7) + ((lane >> 4) & 1) * 8;
    const int bcol = ((lane >> 3) & 1) * 8;

    int buf = 0, ld = 3;
    #pragma unroll 1
    for (int ks = 0; ks < 16; ks++) {
        if (ks + 3 < 16) {
            CP_WAIT(2);
            __syncthreads();
            LOAD_STAGE(ld, ks + 3);
            CP_COMMIT();
        } else {
            CP_WAIT(0);
            __syncthreads();
        }

        uint32_t base = sbase + buf * STG_SZ;
        #pragma unroll
        for (int sub = 0; sub < 2; sub++) {
            int kb = sub * 16;
            uint32_t ah[3][4], bh[2][4];
            #pragma unroll
            for (int mt = 0; mt < 3; mt++)
                LDSM4(ah[mt], base + (uint32_t)((arow + mt * 16) * ASTR + kb + acol) * 2);
            #pragma unroll
            for (int ng = 0; ng < 2; ng++)
                LDSM4(bh[ng], base + STG_A + (uint32_t)((brow + ng * 16) * ASTR + kb + bcol) * 2);
            #pragma unroll
            for (int mt = 0; mt < 3; mt++) {
                #pragma unroll
                for (int nf = 0; nf < 4; nf++)
                    mma_f16(acc[mt][nf], ah[mt], &bh[nf >> 1][(nf & 1) * 2]);
            }
        }
        __syncthreads();
        buf = (buf + 1) & 3;
        ld  = (ld  + 1) & 3;
    }

    // ========== epilogue: att@G on tensor cores ==========
    // sGt: [2 batches][128 cols][64 halfs] (G transposed, fp16) = 32768 B
    // sAtt: [48 rows][64 halfs] fp16 A operand                  =  6144 B
    __half* sGt  = (__half*)smem;
    __half* sAtt = (__half*)(smem + 32768);
    const uint32_t sGt_u  = sbase;
    const uint32_t sAtt_u = sbase + 32768;

    #pragma unroll
    for (int mt = 0; mt < 3; mt++) {
        int row = wm * 48 + mt * 16 + (lane >> 2);   // 0..95 (stays in one batch)
        int b2 = row >= 48, ml = row - b2 * 48;
        #pragma unroll
        for (int nf = 0; nf < 4; nf++) {
            int col = wn * 32 + nf * 8 + (lane & 3) * 2;
            __half* p = sGt + (size_t)(b2 * 128 + col) * 64;
            p[ml]          = __float2half_rn(acc[mt][nf][0]);
            p[64 + ml]     = __float2half_rn(acc[mt][nf][1]);
            p[ml + 8]      = __float2half_rn(acc[mt][nf][2]);
            p[64 + ml + 8] = __float2half_rn(acc[mt][nf][3]);
        }
    }
    for (int i = tid; i < 2304; i += 256)
        sAtt[(i / 48) * 64 + (i % 48)] = __float2half_rn(__ldg(att + i));
    __syncthreads();

    // second MMA: out[n][col] = sum_m att[n][m] * G[m][col]; M=48,N=16/warp,K=48
    {
        const int c0 = wid * 16;
        const int ar2 = lane & 15;
        const int ac2 = (lane >> 4) * 8;
        const int br2 = (lane & 7) + ((lane >> 4) & 1) * 8;
        const int bc2 = ((lane >> 3) & 1) * 8;

        #pragma unroll
        for (int b2 = 0; b2 < 2; b2++) {
            float o[3][2][4];
            #pragma unroll
            for (int mt = 0; mt < 3; mt++)
                #pragma unroll
                for (int nfi = 0; nfi < 2; nfi++)
                    #pragma unroll
                    for (int r = 0; r < 4; r++) o[mt][nfi][r] = 0.f;

            #pragma unroll
            for (int kt = 0; kt < 3; kt++) {
                uint32_t af[3][4], bf[4];
                #pragma unroll
                for (int mt = 0; mt < 3; mt++)
                    LDSM4(af[mt], sAtt_u +
                          (uint32_t)((mt * 16 + ar2) * 64 + kt * 16 + ac2) * 2);
                LDSM4(bf, sGt_u +
                      (uint32_t)((b2 * 128 + c0 + br2) * 64 + kt * 16 + bc2) * 2);
                #pragma unroll
                for (int mt = 0; mt < 3; mt++) {
                    mma_f16(o[mt][0], af[mt], &bf[0]);
                    mma_f16(o[mt][1], af[mt], &bf[2]);
                }
            }

            #pragma unroll
            for (int nfi = 0; nfi < 2; nfi++) {
                int col = n0 + c0 + nfi * 8 + (lane & 3) * 2;
                float2 bb = *(const float2*)&bias[col];
                #pragma unroll
                for (int mt = 0; mt < 3; mt++) {
                    int nloc = mt * 16 + (lane >> 2);
                    int gr0 = m0 + b2 * 48 + nloc;
                    int gr1 = gr0 + 8;
                    float v0 = ftanh(o[mt][nfi][0] + bb.x);
                    float v1 = ftanh(o[mt][nfi][1] + bb.y);
                    float v2 = ftanh(o[mt][nfi][2] + bb.x);
                    float v3 = ftanh(o[mt][nfi][3] + bb.y);
                    size_t x0 = (size_t)gr0 * 512 + col;
                    size_t x1 = (size_t)gr1 * 512 + col;
                    if (residual) {
                        float2 a0 = *(const float2*)&g_X[x0];
                        float2 a1 = *(const float2*)&g_X[x1];
                        v0 += a0.x; v1 += a0.y; v2 += a1.x; v3 += a1.y;
                        *(float2*)&g_X[x0] = make_float2(v0, v1);
                        *(float2*)&g_X[x1] = make_float2(v2, v3);
                    }
                    if (emit) {
                        *(__half2*)&g_Af[x0] =
                            __halves2half2(__float2half_rn(v0), __float2half_rn(v1));
                        *(__half2*)&g_Af[x1] =
                            __halves2half2(__float2half_rn(v2), __float2half_rn(v3));
                    }
                }
            }
        }
    }
}

// ======================= tail: gc7 + fused + MLP (warp-dot) ================
#define TAIL_SMEM ((24576 + 5120 + 480 + 480 + 480 + 1920 + 2560) * 4)
__global__ void __launch_bounds__(512)
tail_kernel(const float* __restrict__ gc7_w, const float* __restrict__ gc7_att,
            const float* __restrict__ gc7_b, const float* __restrict__ mlp_w1,
            const float* __restrict__ mlp_w2, float* __restrict__ out) {
    extern __shared__ float sm[];
    float* sY    = sm;
    float* sW7   = sm + 24576;
    float* sDct  = sm + 29696;
    float* sP    = sm + 30176;
    float* sOut  = sm + 30656;
    float* sFused= sm + 31136;
    float* sW2   = sm + 33056;
    float* sH    = sm;

    const int tid = threadIdx.x, b = blockIdx.x;
    const int lane = tid & 31, w = tid >> 5;

    {
        const float4* ysrc = (const float4*)(g_X + (size_t)b * 24576);
        float4* ydst = (float4*)sY;
        #pragma unroll
        for (int i = 0; i < 12; i++) ydst[tid + i * 512] = ysrc[tid + i * 512];
    }
    for (int i = tid; i < 5120; i += 512) {
        int o = i >> 9, k = i & 511;
        sW7[i] = __ldg(gc7_w + k * 10 + o);
    }
    for (int i = tid; i < 2560; i += 512) sW2[i] = __ldg(mlp_w2 + i);
    if (tid < 480) sDct[tid] = g_dct[b * 480 + tid];
    __syncthreads();

    #pragma unroll 1
    for (int uu = 0; uu < 30; uu++) {
        int u = uu * 16 + w;
        int m = u / 10, o = u % 10;
        const float* yr = sY + m * 512;
        const float* wr = sW7 + o * 512;
        float a = 0.f;
        #pragma unroll
        for (int j = 0; j < 16; j++) a += yr[j * 32 + lane] * wr[j * 32 + lane];
        a += __shfl_xor_sync(0xFFFFFFFFu, a, 16);
        a += __shfl_xor_sync(0xFFFFFFFFu, a, 8);
        a += __shfl_xor_sync(0xFFFFFFFFu, a, 4);
        a += __shfl_xor_sync(0xFFFFFFFFu, a, 2);
        a += __shfl_xor_sync(0xFFFFFFFFu, a, 1);
        if (lane == 0) sP[u] = a;
    }
    __syncthreads();

    if (tid < 480) {
        int n = tid / 10, o = tid % 10;
        float a = __ldg(gc7_b + o) + sDct[tid];
        for (int m = 0; m < 48; m++) a += __ldg(gc7_att + n * 48 + m) * sP[m * 10 + o];
        sOut[tid] = a;
    }
    __syncthreads();

    for (int i = tid; i < 1920; i += 512) {
        int f = i % 48, t = i / 48;
        float v;
        if (t < 30) {
            v = 0.f;
            #pragma unroll
            for (int d = 0; d < 10; d++) {
                float wd = (d == 0) ? W0_DCT : W1_DCT;
                v += wd * cosf(PI_F * ((float)t + 0.5f) * (float)d / 30.0f)
                        * sOut[f * 10 + d];
            }
        } else v = g_ffc[b * 480 + f * 10 + (t - 30)];
        sFused[f * 40 + t] = v;
    }
    __syncthreads();

    {
        int o = tid & 255, fg = tid >> 8;
        float w1r[40];
        #pragma unroll
        for (int t = 0; t < 40; t++) w1r[t] = __ldg(mlp_w1 + o * 40 + t);
        for (int f = fg * 24; f < fg * 24 + 24; f++) {
            float a = 0.f;
            #pragma unroll
            for (int t = 0; t < 40; t++) a += w1r[t] * sFused[f * 40 + t];
            sH[f * 256 + o] = (a > 0.f) ? a : 0.f;
        }
    }
    __syncthreads();

    #pragma unroll 1
    for (int uu = 0; uu < 30; uu++) {
        int u = uu * 16 + w;
        int f = u / 10, t2 = u % 10;
        const float* hr = sH + f * 256;
        const float* wr = sW2 + t2 * 256;
        float a = 0.f;
        #pragma unroll
        for (int j = 0; j < 8; j++) a += hr[j * 32 + lane] * wr[j * 32 + lane];
        a += __shfl_xor_sync(0xFFFFFFFFu, a, 16);
        a += __shfl_xor_sync(0xFFFFFFFFu, a, 8);
        a += __shfl_xor_sync(0xFFFFFFFFu, a, 4);
        a += __shfl_xor_sync(0xFFFFFFFFu, a, 2);
        a += __shfl_xor_sync(0xFFFFFFFFu, a, 1);
        if (lane == 0) out[b * 480 + t2 * 48 + f] = a;
    }
}

// ===========================================================================
extern "C" void kernel_launch(void* const* d_in, const int* in_sizes, int n_in,
                              void* d_out, int out_size) {
    const float* seq     = (const float*)d_in[0];
    const float* gc1_w   = (const float*)d_in[5];
    const float* gc1_att = (const float*)d_in[6];
    const float* gc1_b   = (const float*)d_in[7];
    const float* gcb_w   = (const float*)d_in[8];
    const float* gcb_att = (const float*)d_in[9];
    const float* gcb_b   = (const float*)d_in[10];
    const float* gc7_w   = (const float*)d_in[11];
    const float* gc7_att = (const float*)d_in[12];
    const float* gc7_b   = (const float*)d_in[13];
    const float* mlp_w1  = (const float*)d_in[14];
    const float* mlp_w2  = (const float*)d_in[15];
    const float* ffc_wl  = (const float*)d_in[16];
    const float* ffc_wg  = (const float*)d_in[17];
    float* out = (float*)d_out;

    int B = in_sizes[0] / 2400;           // 1024
    int gm = (B * 48) / 96;               // 512 m-tiles

    cudaFuncSetAttribute(layer_kernel,
        cudaFuncAttributeMaxDynamicSharedMemorySize, GEMM_SMEM);
    cudaFuncSetAttribute(tail_kernel,
        cudaFuncAttributeMaxDynamicSharedMemorySize, TAIL_SMEM);

    prep_w_kernel<<<4096, 256>>>(gcb_w);
    head_kernel<<<B, 512>>>(seq, ffc_wl, ffc_wg, gc1_w, gc1_att, gc1_b);

    for (int l = 0; l < 4; l++) {
        layer_kernel<<<dim3(4, gm), 256, GEMM_SMEM>>>(
            l, l & 1, (l < 3) ? 1 : 0,
            gcb_att + l * 2304, gcb_b + l * 512);
    }
    tail_kernel<<<B, 512, TAIL_SMEM>>>(gc7_w, gc7_att, gc7_b,
                                       mlp_w1, mlp_w2, out);
}